// round 10
// baseline (speedup 1.0000x reference)
#include <cuda_runtime.h>

// MyMaxPool: 2x2 stride-2 pooling over [C=64, H=512, W=512] fp32 with the
// MaxNetwork pair op  f(a,b) = relu(relu(a-b) + relu(b)).
// Output [64, 256, 256] fp32.
//
// Pure HBM-streaming: each thread loads 2x float4 from input row 2*oh and
// 2x float4 from row 2*oh+1 (covering 8 input columns = 4 output windows),
// computes 4 outputs, stores one float4. 64B in / 16B out per thread,
// fully coalesced, 16B aligned.

#define C_    64
#define H_    512
#define W_    512
#define OH_   256
#define OW_   256

__device__ __forceinline__ float pairmax_net(float a, float b) {
    // relu(relu(a-b) + relu(b)); outer relu is a no-op (sum of relus >= 0)
    return fmaxf(a - b, 0.0f) + fmaxf(b, 0.0f);
}

__global__ __launch_bounds__(256)
void maxpool_net_kernel(const float* __restrict__ x, float* __restrict__ out) {
    // Each thread produces 4 consecutive output columns.
    // total threads = C*OH*OW/4 = 64*256*256/4 = 1,048,576
    const int tid = blockIdx.x * blockDim.x + threadIdx.x;

    // quad index within an output row: 0..63 (OW/4)
    const int ow4 = tid & 63;
    const int oh  = (tid >> 6) & (OH_ - 1);
    const int c   = tid >> 14;              // tid / (64*256)

    // input base: channel c, row 2*oh, col 8*ow4
    const float4* __restrict__ xin =
        reinterpret_cast<const float4*>(x) +
        ((size_t)c * (H_ * W_ / 4) + (size_t)(2 * oh) * (W_ / 4) + 2 * ow4);

    // front-batch all 4 loads (MLP=4)
    const float4 t0 = __ldg(xin);                 // top row, cols [8w .. 8w+3]
    const float4 t1 = __ldg(xin + 1);             // top row, cols [8w+4 .. 8w+7]
    const float4 b0 = __ldg(xin + (W_ / 4));      // bottom row
    const float4 b1 = __ldg(xin + (W_ / 4) + 1);

    float4 o;
    // window j:   top = (t.x, t.y) | bottom = (b.x, b.y), order (0,0),(0,1),(1,0),(1,1)
    o.x = pairmax_net(pairmax_net(t0.x, t0.y), pairmax_net(b0.x, b0.y));
    o.y = pairmax_net(pairmax_net(t0.z, t0.w), pairmax_net(b0.z, b0.w));
    o.z = pairmax_net(pairmax_net(t1.x, t1.y), pairmax_net(b1.x, b1.y));
    o.w = pairmax_net(pairmax_net(t1.z, t1.w), pairmax_net(b1.z, b1.w));

    float4* __restrict__ dst =
        reinterpret_cast<float4*>(out) +
        ((size_t)c * (OH_ * OW_ / 4) + (size_t)oh * (OW_ / 4) + ow4);
    *dst = o;
}

extern "C" void kernel_launch(void* const* d_in, const int* in_sizes, int n_in,
                              void* d_out, int out_size) {
    const float* x = (const float*)d_in[0];
    float* out = (float*)d_out;

    const int total_threads = C_ * OH_ * OW_ / 4;   // 1,048,576
    const int block = 256;
    const int grid = total_threads / block;          // 4096

    maxpool_net_kernel<<<grid, block>>>(x, out);
}

// round 12
// speedup vs baseline: 1.0029x; 1.0029x over previous
#include <cuda_runtime.h>

// MyMaxPool: 2x2 stride-2 pooling over [C=64, H=512, W=512] fp32 with the
// MaxNetwork pair op  f(a,b) = relu(relu(a-b) + relu(b)).
// Output [64, 256, 256] fp32.
//
// Pure HBM-streaming: each thread loads 2x float4 from input row 2*oh and
// 2x float4 from row 2*oh+1 (covering 8 input columns = 4 output windows),
// computes 4 outputs, stores one float4. 64B in / 16B out per thread,
// fully coalesced, 16B aligned.

#define C_    64
#define H_    512
#define W_    512
#define OH_   256
#define OW_   256

__device__ __forceinline__ float pairmax_net(float a, float b) {
    // relu(relu(a-b) + relu(b)); outer relu is a no-op (sum of relus >= 0)
    return fmaxf(a - b, 0.0f) + fmaxf(b, 0.0f);
}

__global__ __launch_bounds__(256)
void maxpool_net_kernel(const float* __restrict__ x, float* __restrict__ out) {
    // Each thread produces 4 consecutive output columns.
    // total threads = C*OH*OW/4 = 64*256*256/4 = 1,048,576
    const int tid = blockIdx.x * blockDim.x + threadIdx.x;

    // quad index within an output row: 0..63 (OW/4)
    const int ow4 = tid & 63;
    const int oh  = (tid >> 6) & (OH_ - 1);
    const int c   = tid >> 14;              // tid / (64*256)

    // input base: channel c, row 2*oh, col 8*ow4
    const float4* __restrict__ xin =
        reinterpret_cast<const float4*>(x) +
        ((size_t)c * (H_ * W_ / 4) + (size_t)(2 * oh) * (W_ / 4) + 2 * ow4);

    // front-batch all 4 loads (MLP=4)
    const float4 t0 = __ldg(xin);                 // top row, cols [8w .. 8w+3]
    const float4 t1 = __ldg(xin + 1);             // top row, cols [8w+4 .. 8w+7]
    const float4 b0 = __ldg(xin + (W_ / 4));      // bottom row
    const float4 b1 = __ldg(xin + (W_ / 4) + 1);

    float4 o;
    // window j:   top = (t.x, t.y) | bottom = (b.x, b.y), order (0,0),(0,1),(1,0),(1,1)
    o.x = pairmax_net(pairmax_net(t0.x, t0.y), pairmax_net(b0.x, b0.y));
    o.y = pairmax_net(pairmax_net(t0.z, t0.w), pairmax_net(b0.z, b0.w));
    o.z = pairmax_net(pairmax_net(t1.x, t1.y), pairmax_net(b1.x, b1.y));
    o.w = pairmax_net(pairmax_net(t1.z, t1.w), pairmax_net(b1.z, b1.w));

    float4* __restrict__ dst =
        reinterpret_cast<float4*>(out) +
        ((size_t)c * (OH_ * OW_ / 4) + (size_t)oh * (OW_ / 4) + ow4);
    *dst = o;
}

extern "C" void kernel_launch(void* const* d_in, const int* in_sizes, int n_in,
                              void* d_out, int out_size) {
    const float* x = (const float*)d_in[0];
    float* out = (float*)d_out;

    const int total_threads = C_ * OH_ * OW_ / 4;   // 1,048,576
    const int block = 256;
    const int grid = total_threads / block;          // 4096

    maxpool_net_kernel<<<grid, block>>>(x, out);
}

// round 13
// speedup vs baseline: 1.0239x; 1.0209x over previous
#include <cuda_runtime.h>

// MyMaxPool: 2x2 stride-2 pooling over [C=64, H=512, W=512] fp32 with the
// MaxNetwork pair op  f(a,b) = relu(relu(a-b) + relu(b)).
// Output [64, 256, 256] fp32.
//
// Pure HBM-streaming: each thread loads 2x float4 from input row 2*oh and
// 2x float4 from row 2*oh+1 (covering 8 input columns = 4 output windows),
// computes 4 outputs, stores one float4. 64B in / 16B out per thread,
// fully coalesced, 16B aligned.

#define C_    64
#define H_    512
#define W_    512
#define OH_   256
#define OW_   256

__device__ __forceinline__ float pairmax_net(float a, float b) {
    // relu(relu(a-b) + relu(b)); outer relu is a no-op (sum of relus >= 0)
    return fmaxf(a - b, 0.0f) + fmaxf(b, 0.0f);
}

__global__ __launch_bounds__(256)
void maxpool_net_kernel(const float* __restrict__ x, float* __restrict__ out) {
    // Each thread produces 4 consecutive output columns.
    // total threads = C*OH*OW/4 = 64*256*256/4 = 1,048,576
    const int tid = blockIdx.x * blockDim.x + threadIdx.x;

    // quad index within an output row: 0..63 (OW/4)
    const int ow4 = tid & 63;
    const int oh  = (tid >> 6) & (OH_ - 1);
    const int c   = tid >> 14;              // tid / (64*256)

    // input base: channel c, row 2*oh, col 8*ow4
    const float4* __restrict__ xin =
        reinterpret_cast<const float4*>(x) +
        ((size_t)c * (H_ * W_ / 4) + (size_t)(2 * oh) * (W_ / 4) + 2 * ow4);

    // front-batch all 4 loads (MLP=4)
    const float4 t0 = __ldg(xin);                 // top row, cols [8w .. 8w+3]
    const float4 t1 = __ldg(xin + 1);             // top row, cols [8w+4 .. 8w+7]
    const float4 b0 = __ldg(xin + (W_ / 4));      // bottom row
    const float4 b1 = __ldg(xin + (W_ / 4) + 1);

    float4 o;
    // window j:   top = (t.x, t.y) | bottom = (b.x, b.y), order (0,0),(0,1),(1,0),(1,1)
    o.x = pairmax_net(pairmax_net(t0.x, t0.y), pairmax_net(b0.x, b0.y));
    o.y = pairmax_net(pairmax_net(t0.z, t0.w), pairmax_net(b0.z, b0.w));
    o.z = pairmax_net(pairmax_net(t1.x, t1.y), pairmax_net(b1.x, b1.y));
    o.w = pairmax_net(pairmax_net(t1.z, t1.w), pairmax_net(b1.z, b1.w));

    float4* __restrict__ dst =
        reinterpret_cast<float4*>(out) +
        ((size_t)c * (OH_ * OW_ / 4) + (size_t)oh * (OW_ / 4) + ow4);
    *dst = o;
}

extern "C" void kernel_launch(void* const* d_in, const int* in_sizes, int n_in,
                              void* d_out, int out_size) {
    const float* x = (const float*)d_in[0];
    float* out = (float*)d_out;

    const int total_threads = C_ * OH_ * OW_ / 4;   // 1,048,576
    const int block = 256;
    const int grid = total_threads / block;          // 4096

    maxpool_net_kernel<<<grid, block>>>(x, out);
}